// round 8
// baseline (speedup 1.0000x reference)
#include <cuda_runtime.h>
#include <cuda_bf16.h>
#include <cstdint>

// Problem constants (fixed by the dataset)
#define N_NODES 100000
#define N_EDGES 1250000
#define IN_CH   128
#define OUT_CH  64

#define SCAN_BLK   1024
#define N_SCAN_BLK ((N_NODES + SCAN_BLK - 1) / SCAN_BLK)   // 98

// Scratch (no cudaMalloc allowed)
__device__ __align__(16) float g_h[(size_t)N_NODES * OUT_CH];   // 25.6 MB
__device__ float g_dis[N_NODES];            // deg, then deg^-1/2
__device__ int   g_cnt[N_NODES];            // in-degree (edge count)
__device__ int   g_off[N_NODES];            // excl. prefix -> end cursor after fill
__device__ int   g_bsum[N_SCAN_BLK];        // scan block sums
__device__ __align__(8) int2 g_edge[N_EDGES]; // CSR payload: {col, bits(dis[col])}
__device__ int   g_is64;                    // 1 if edge_index stored as int64

// ---------------------------------------------------------------------------
// Edge-index access through an int32 view, layout-agnostic.
// ---------------------------------------------------------------------------
__device__ __forceinline__ int edge_row(const int* __restrict__ w, int e, int is64) {
    return is64 ? w[2 * e] : w[e];
}
__device__ __forceinline__ int edge_col(const int* __restrict__ w, int e, int is64) {
    return is64 ? w[2 * (N_EDGES + e)] : w[N_EDGES + e];
}

// ---------------------------------------------------------------------------
// f32x2 packed-FMA helpers (sm_100+; ptxas emits FFMA2). Compute-only asm.
// ---------------------------------------------------------------------------
__device__ __forceinline__ void fma2(unsigned long long& acc,
                                     unsigned long long a,
                                     unsigned long long b) {
    asm("fma.rn.f32x2 %0, %1, %2, %0;" : "+l"(acc) : "l"(a), "l"(b));
}
__device__ __forceinline__ unsigned long long pack2(float lo, float hi) {
    unsigned long long r;
    asm("mov.b64 %0, {%1, %2};" : "=l"(r) : "f"(lo), "f"(hi));
    return r;
}
__device__ __forceinline__ float2 unpack2(unsigned long long v) {
    float2 f;
    asm("mov.b64 {%0, %1}, %2;" : "=f"(f.x), "=f"(f.y) : "l"(v));
    return f;
}

// ---------------------------------------------------------------------------
// 1) zero degree+count buffers; block 0 also detects edge_index dtype
//    (odd 32-bit words all zero over 1024 samples => int64 storage).
// ---------------------------------------------------------------------------
__global__ void k_zero_detect(const int* __restrict__ w) {
    __shared__ int nz;
    int i = blockIdx.x * blockDim.x + threadIdx.x;
    if (i < N_NODES) { g_dis[i] = 0.0f; g_cnt[i] = 0; }
    if (blockIdx.x == 0) {
        if (threadIdx.x == 0) nz = 0;
        __syncthreads();
        int bad = 0;
        #pragma unroll
        for (int j = 0; j < 4; j++) {
            int idx = 2 * (threadIdx.x + j * 256) + 1;
            if (w[idx] != 0) bad = 1;
        }
        if (bad) atomicOr(&nz, 1);
        __syncthreads();
        if (threadIdx.x == 0) g_is64 = (nz == 0) ? 1 : 0;
    }
}

// ---------------------------------------------------------------------------
// 2) fused weighted in-degree + edge histogram
// ---------------------------------------------------------------------------
__global__ void k_deg_accum(const int* __restrict__ ei,
                            const float* __restrict__ ew) {
    int e = blockIdx.x * blockDim.x + threadIdx.x;
    if (e < N_EDGES) {
        int is64 = g_is64;
        int r = edge_row(ei, e, is64);
        if ((unsigned)r < N_NODES) {
            atomicAdd(&g_dis[r], ew[e]);
            atomicAdd(&g_cnt[r], 1);
        }
    }
}

// ---------------------------------------------------------------------------
// 3a) scan step 1 (+ fused deg^-1/2): per-block exclusive scan of g_cnt
// ---------------------------------------------------------------------------
__global__ void __launch_bounds__(SCAN_BLK) k_scan1() {
    __shared__ int s[SCAN_BLK];
    int t = threadIdx.x;
    int i = blockIdx.x * SCAN_BLK + t;
    int v = (i < N_NODES) ? g_cnt[i] : 0;
    s[t] = v;
    // fused: deg -> deg^-1/2 (independent of the scan)
    if (i < N_NODES) {
        float d = g_dis[i];
        g_dis[i] = (d > 0.0f) ? rsqrtf(d) : 0.0f;
    }
    __syncthreads();
    #pragma unroll
    for (int off = 1; off < SCAN_BLK; off <<= 1) {
        int x = (t >= off) ? s[t - off] : 0;
        __syncthreads();
        s[t] += x;
        __syncthreads();
    }
    if (i < N_NODES) g_off[i] = s[t] - v;          // exclusive
    if (t == SCAN_BLK - 1) g_bsum[blockIdx.x] = s[t];
}

// ---------------------------------------------------------------------------
// 3b) scan step 2: parallel exclusive scan of 98 block sums (1 block, 128 thr)
// ---------------------------------------------------------------------------
__global__ void k_scan2() {
    __shared__ int s[128];
    int t = threadIdx.x;
    int v = (t < N_SCAN_BLK) ? g_bsum[t] : 0;
    s[t] = v;
    __syncthreads();
    #pragma unroll
    for (int off = 1; off < 128; off <<= 1) {
        int x = (t >= off) ? s[t - off] : 0;
        __syncthreads();
        s[t] += x;
        __syncthreads();
    }
    if (t < N_SCAN_BLK) g_bsum[t] = s[t] - v;      // exclusive
}

// ---------------------------------------------------------------------------
// 3c) scan step 3: add block offsets
// ---------------------------------------------------------------------------
__global__ void __launch_bounds__(SCAN_BLK) k_scan3() {
    int i = blockIdx.x * SCAN_BLK + threadIdx.x;
    if (i < N_NODES) g_off[i] += g_bsum[blockIdx.x];
}

// ---------------------------------------------------------------------------
// 4) CSR fill: g_off used as cursor; after this, g_off[r] = end of node r.
//    Payload packs {col, dis[col]} so the gather never touches ei/dis again.
// ---------------------------------------------------------------------------
__global__ void k_fill(const int* __restrict__ ei) {
    int e = blockIdx.x * blockDim.x + threadIdx.x;
    if (e < N_EDGES) {
        int is64 = g_is64;
        int r   = edge_row(ei, e, is64);
        int col = edge_col(ei, e, is64);
        if ((unsigned)r >= N_NODES || (unsigned)col >= N_NODES) return;
        int pos = atomicAdd(&g_off[r], 1);
        g_edge[pos] = make_int2(col, __float_as_int(g_dis[col]));
    }
}

// ---------------------------------------------------------------------------
// 5) GEMM: g_h[100000,64] = x[100000,128] @ W[128,64]  (FFMA2, tiled)
// ---------------------------------------------------------------------------
#define XS_STRIDE 68

__global__ void __launch_bounds__(256) k_gemm(const float* __restrict__ x,
                                              const float* __restrict__ W) {
    __shared__ __align__(16) float Ws[IN_CH * OUT_CH];   // 32 KB
    __shared__ __align__(16) float Xs[64 * XS_STRIDE];   // 17 KB

    const int t  = threadIdx.x;
    const int tx = t & 15;
    const int ty = t >> 4;
    const int nb = blockIdx.x * 64;

    {
        const float4* W4 = reinterpret_cast<const float4*>(W);
        float4* Ws4 = reinterpret_cast<float4*>(Ws);
        #pragma unroll
        for (int i = 0; i < (IN_CH * OUT_CH / 4) / 256; i++)
            Ws4[t + i * 256] = W4[t + i * 256];
    }

    unsigned long long acc[4][2];
    #pragma unroll
    for (int i = 0; i < 4; i++) { acc[i][0] = 0ull; acc[i][1] = 0ull; }

    #pragma unroll
    for (int kc = 0; kc < 2; kc++) {
        {
            const float4* x4 = reinterpret_cast<const float4*>(x);
            #pragma unroll
            for (int i = 0; i < 4; i++) {
                int f = t + i * 256;
                int node = f >> 4;
                int kk4  = f & 15;
                int gn = nb + node;
                float4 v = make_float4(0.f, 0.f, 0.f, 0.f);
                if (gn < N_NODES)
                    v = x4[(size_t)gn * (IN_CH / 4) + kc * 16 + kk4];
                *reinterpret_cast<float4*>(&Xs[node * XS_STRIDE + kk4 * 4]) = v;
            }
        }
        __syncthreads();

        #pragma unroll 8
        for (int kk = 0; kk < 64; kk++) {
            float4 w = *reinterpret_cast<const float4*>(
                &Ws[(kc * 64 + kk) * OUT_CH + tx * 4]);
            unsigned long long wA = pack2(w.x, w.y);
            unsigned long long wB = pack2(w.z, w.w);
            #pragma unroll
            for (int i = 0; i < 4; i++) {
                float xv = Xs[(ty * 4 + i) * XS_STRIDE + kk];
                unsigned long long x2 = pack2(xv, xv);
                fma2(acc[i][0], x2, wA);
                fma2(acc[i][1], x2, wB);
            }
        }
        __syncthreads();
    }

    #pragma unroll
    for (int i = 0; i < 4; i++) {
        int node = nb + ty * 4 + i;
        if (node < N_NODES) {
            float2 a = unpack2(acc[i][0]);
            float2 b = unpack2(acc[i][1]);
            float4 v = make_float4(a.x, a.y, b.x, b.y);
            *reinterpret_cast<float4*>(&g_h[(size_t)node * OUT_CH + tx * 4]) = v;
        }
    }
}

// ---------------------------------------------------------------------------
// 6) atomic-free gather: one warp per node; HALF-WARP per edge (16 lanes x
//    float4 = full 256B row), 2 edges per step, unrolled x2 -> 4 loads in
//    flight. Cross-half reduce via shfl_xor(16); lanes 0-15 store.
// ---------------------------------------------------------------------------
__global__ void __launch_bounds__(256) k_gather(const float* __restrict__ b,
                                                float* __restrict__ out) {
    int warp = (blockIdx.x * blockDim.x + threadIdx.x) >> 5;
    int lane = threadIdx.x & 31;
    if (warp >= N_NODES) return;

    int end = g_off[warp];          // post-fill cursor = end
    int deg = g_cnt[warp];
    const int2* ep = g_edge + (end - deg);

    const int half = lane >> 4;     // 0: even edges, 1: odd edges
    const int l16  = lane & 15;     // channel group: l16*4 .. l16*4+3
    const float4* h4 = reinterpret_cast<const float4*>(g_h);

    float4 acc = make_float4(0.f, 0.f, 0.f, 0.f);

    int i = 0;
    for (; i + 4 <= deg; i += 4) {
        int2 p0 = ep[i + half];
        int2 p1 = ep[i + 2 + half];
        float s0 = __int_as_float(p0.y);
        float s1 = __int_as_float(p1.y);
        float4 h0 = h4[(size_t)p0.x * (OUT_CH / 4) + l16];
        float4 h1 = h4[(size_t)p1.x * (OUT_CH / 4) + l16];
        acc.x += h0.x * s0 + h1.x * s1;
        acc.y += h0.y * s0 + h1.y * s1;
        acc.z += h0.z * s0 + h1.z * s1;
        acc.w += h0.w * s0 + h1.w * s1;
    }
    if (i + 2 <= deg) {
        int2 p0 = ep[i + half];
        float s0 = __int_as_float(p0.y);
        float4 h0 = h4[(size_t)p0.x * (OUT_CH / 4) + l16];
        acc.x += h0.x * s0; acc.y += h0.y * s0;
        acc.z += h0.z * s0; acc.w += h0.w * s0;
        i += 2;
    }
    if (i < deg && half == 0) {     // odd tail handled by half 0
        int2 p0 = ep[i];
        float s0 = __int_as_float(p0.y);
        float4 h0 = h4[(size_t)p0.x * (OUT_CH / 4) + l16];
        acc.x += h0.x * s0; acc.y += h0.y * s0;
        acc.z += h0.z * s0; acc.w += h0.w * s0;
    }

    // combine the two half-warps (lane l and l+16 hold the same channels)
    acc.x += __shfl_xor_sync(0xffffffffu, acc.x, 16);
    acc.y += __shfl_xor_sync(0xffffffffu, acc.y, 16);
    acc.z += __shfl_xor_sync(0xffffffffu, acc.z, 16);
    acc.w += __shfl_xor_sync(0xffffffffu, acc.w, 16);

    if (half == 0) {
        float dr = g_dis[warp];
        float4 bv = reinterpret_cast<const float4*>(b)[l16];
        float4 o = make_float4(acc.x * dr + bv.x, acc.y * dr + bv.y,
                               acc.z * dr + bv.z, acc.w * dr + bv.w);
        reinterpret_cast<float4*>(out)[(size_t)warp * (OUT_CH / 4) + l16] = o;
    }
}

// ---------------------------------------------------------------------------
// launch
// ---------------------------------------------------------------------------
extern "C" void kernel_launch(void* const* d_in, const int* in_sizes, int n_in,
                              void* d_out, int out_size) {
    const float* x  = (const float*)d_in[0];
    const int*   ei = (const int*)d_in[1];     // int32 view; layout detected on-device
    const float* ew = (const float*)d_in[2];
    const float* W  = (const float*)d_in[3];
    const float* b  = (const float*)d_in[4];
    float* out = (float*)d_out;

    k_zero_detect<<<(N_NODES + 255) / 256, 256>>>(ei);
    k_deg_accum<<<(N_EDGES + 255) / 256, 256>>>(ei, ew);

    // CSR build (scan1 also finalizes deg^-1/2)
    k_scan1<<<N_SCAN_BLK, SCAN_BLK>>>();
    k_scan2<<<1, 128>>>();
    k_scan3<<<N_SCAN_BLK, SCAN_BLK>>>();
    k_fill<<<(N_EDGES + 255) / 256, 256>>>(ei);

    // dense transform
    k_gemm<<<(N_NODES + 63) / 64, 256>>>(x, W);

    // atomic-free aggregate + bias
    int gather_blocks = (N_NODES * 32 + 255) / 256;
    k_gather<<<gather_blocks, 256>>>(b, out);
}

// round 9
// speedup vs baseline: 1.3632x; 1.3632x over previous
#include <cuda_runtime.h>
#include <cuda_bf16.h>
#include <cstdint>

// Problem constants (fixed by the dataset)
#define N_NODES 100000
#define N_EDGES 1250000
#define IN_CH   128
#define OUT_CH  64

#define SCAN_BLK   1024
#define N_SCAN_BLK ((N_NODES + SCAN_BLK - 1) / SCAN_BLK)   // 98

// Scratch (no cudaMalloc allowed)
__device__ __align__(16) float g_h[(size_t)N_NODES * OUT_CH];   // 25.6 MB
__device__ float g_dis[N_NODES];            // deg, then deg^-1/2
__device__ int   g_cnt[N_NODES];            // in-degree (edge count)
__device__ int   g_off[N_NODES];            // excl. prefix -> end cursor after fill
__device__ int   g_bsum[N_SCAN_BLK];        // scan block sums
__device__ __align__(8) int2 g_edge[N_EDGES]; // CSR payload: {col, bits(dis[col])}
__device__ int   g_is64;                    // 1 if edge_index stored as int64

// ---------------------------------------------------------------------------
// Edge-index access through an int32 view, layout-agnostic.
// ---------------------------------------------------------------------------
__device__ __forceinline__ int edge_row(const int* __restrict__ w, int e, int is64) {
    return is64 ? w[2 * e] : w[e];
}
__device__ __forceinline__ int edge_col(const int* __restrict__ w, int e, int is64) {
    return is64 ? w[2 * (N_EDGES + e)] : w[N_EDGES + e];
}

// ---------------------------------------------------------------------------
// f32x2 packed-FMA helpers (sm_100+; ptxas emits FFMA2). Compute-only asm.
// ---------------------------------------------------------------------------
__device__ __forceinline__ void fma2(unsigned long long& acc,
                                     unsigned long long a,
                                     unsigned long long b) {
    asm("fma.rn.f32x2 %0, %1, %2, %0;" : "+l"(acc) : "l"(a), "l"(b));
}
__device__ __forceinline__ unsigned long long pack2(float lo, float hi) {
    unsigned long long r;
    asm("mov.b64 %0, {%1, %2};" : "=l"(r) : "f"(lo), "f"(hi));
    return r;
}
__device__ __forceinline__ float2 unpack2(unsigned long long v) {
    float2 f;
    asm("mov.b64 {%0, %1}, %2;" : "=f"(f.x), "=f"(f.y) : "l"(v));
    return f;
}

// ---------------------------------------------------------------------------
// 1) zero degree+count buffers; block 0 also detects edge_index dtype
// ---------------------------------------------------------------------------
__global__ void k_zero_detect(const int* __restrict__ w) {
    __shared__ int nz;
    int i = blockIdx.x * blockDim.x + threadIdx.x;
    if (i < N_NODES) { g_dis[i] = 0.0f; g_cnt[i] = 0; }
    if (blockIdx.x == 0) {
        if (threadIdx.x == 0) nz = 0;
        __syncthreads();
        int bad = 0;
        #pragma unroll
        for (int j = 0; j < 4; j++) {
            int idx = 2 * (threadIdx.x + j * 256) + 1;
            if (w[idx] != 0) bad = 1;
        }
        if (bad) atomicOr(&nz, 1);
        __syncthreads();
        if (threadIdx.x == 0) g_is64 = (nz == 0) ? 1 : 0;
    }
}

// ---------------------------------------------------------------------------
// 2) fused weighted in-degree + edge histogram
// ---------------------------------------------------------------------------
__global__ void k_deg_accum(const int* __restrict__ ei,
                            const float* __restrict__ ew) {
    int e = blockIdx.x * blockDim.x + threadIdx.x;
    if (e < N_EDGES) {
        int is64 = g_is64;
        int r = edge_row(ei, e, is64);
        if ((unsigned)r < N_NODES) {
            atomicAdd(&g_dis[r], ew[e]);
            atomicAdd(&g_cnt[r], 1);
        }
    }
}

// ---------------------------------------------------------------------------
// 3a) scan step 1 (+ fused deg^-1/2): per-block exclusive scan of g_cnt
// ---------------------------------------------------------------------------
__global__ void __launch_bounds__(SCAN_BLK) k_scan1() {
    __shared__ int s[SCAN_BLK];
    int t = threadIdx.x;
    int i = blockIdx.x * SCAN_BLK + t;
    int v = (i < N_NODES) ? g_cnt[i] : 0;
    s[t] = v;
    if (i < N_NODES) {
        float d = g_dis[i];
        g_dis[i] = (d > 0.0f) ? rsqrtf(d) : 0.0f;
    }
    __syncthreads();
    #pragma unroll
    for (int off = 1; off < SCAN_BLK; off <<= 1) {
        int x = (t >= off) ? s[t - off] : 0;
        __syncthreads();
        s[t] += x;
        __syncthreads();
    }
    if (i < N_NODES) g_off[i] = s[t] - v;          // exclusive
    if (t == SCAN_BLK - 1) g_bsum[blockIdx.x] = s[t];
}

// ---------------------------------------------------------------------------
// 3b) scan step 2: parallel exclusive scan of 98 block sums (1 block)
// ---------------------------------------------------------------------------
__global__ void k_scan2() {
    __shared__ int s[128];
    int t = threadIdx.x;
    int v = (t < N_SCAN_BLK) ? g_bsum[t] : 0;
    s[t] = v;
    __syncthreads();
    #pragma unroll
    for (int off = 1; off < 128; off <<= 1) {
        int x = (t >= off) ? s[t - off] : 0;
        __syncthreads();
        s[t] += x;
        __syncthreads();
    }
    if (t < N_SCAN_BLK) g_bsum[t] = s[t] - v;      // exclusive
}

// ---------------------------------------------------------------------------
// 3c) scan step 3: add block offsets
// ---------------------------------------------------------------------------
__global__ void __launch_bounds__(SCAN_BLK) k_scan3() {
    int i = blockIdx.x * SCAN_BLK + threadIdx.x;
    if (i < N_NODES) g_off[i] += g_bsum[blockIdx.x];
}

// ---------------------------------------------------------------------------
// 4) CSR fill: g_off used as cursor; after this, g_off[r] = end of node r.
// ---------------------------------------------------------------------------
__global__ void k_fill(const int* __restrict__ ei) {
    int e = blockIdx.x * blockDim.x + threadIdx.x;
    if (e < N_EDGES) {
        int is64 = g_is64;
        int r   = edge_row(ei, e, is64);
        int col = edge_col(ei, e, is64);
        if ((unsigned)r >= N_NODES || (unsigned)col >= N_NODES) return;
        int pos = atomicAdd(&g_off[r], 1);
        g_edge[pos] = make_int2(col, __float_as_int(g_dis[col]));
    }
}

// ---------------------------------------------------------------------------
// 5) GEMM: g_h[100000,64] = x[100000,128] @ W[128,64]  (FFMA2, tiled)
// ---------------------------------------------------------------------------
#define XS_STRIDE 68

__global__ void __launch_bounds__(256) k_gemm(const float* __restrict__ x,
                                              const float* __restrict__ W) {
    __shared__ __align__(16) float Ws[IN_CH * OUT_CH];   // 32 KB
    __shared__ __align__(16) float Xs[64 * XS_STRIDE];   // 17 KB

    const int t  = threadIdx.x;
    const int tx = t & 15;
    const int ty = t >> 4;
    const int nb = blockIdx.x * 64;

    {
        const float4* W4 = reinterpret_cast<const float4*>(W);
        float4* Ws4 = reinterpret_cast<float4*>(Ws);
        #pragma unroll
        for (int i = 0; i < (IN_CH * OUT_CH / 4) / 256; i++)
            Ws4[t + i * 256] = W4[t + i * 256];
    }

    unsigned long long acc[4][2];
    #pragma unroll
    for (int i = 0; i < 4; i++) { acc[i][0] = 0ull; acc[i][1] = 0ull; }

    #pragma unroll
    for (int kc = 0; kc < 2; kc++) {
        {
            const float4* x4 = reinterpret_cast<const float4*>(x);
            #pragma unroll
            for (int i = 0; i < 4; i++) {
                int f = t + i * 256;
                int node = f >> 4;
                int kk4  = f & 15;
                int gn = nb + node;
                float4 v = make_float4(0.f, 0.f, 0.f, 0.f);
                if (gn < N_NODES)
                    v = x4[(size_t)gn * (IN_CH / 4) + kc * 16 + kk4];
                *reinterpret_cast<float4*>(&Xs[node * XS_STRIDE + kk4 * 4]) = v;
            }
        }
        __syncthreads();

        #pragma unroll 8
        for (int kk = 0; kk < 64; kk++) {
            float4 w = *reinterpret_cast<const float4*>(
                &Ws[(kc * 64 + kk) * OUT_CH + tx * 4]);
            unsigned long long wA = pack2(w.x, w.y);
            unsigned long long wB = pack2(w.z, w.w);
            #pragma unroll
            for (int i = 0; i < 4; i++) {
                float xv = Xs[(ty * 4 + i) * XS_STRIDE + kk];
                unsigned long long x2 = pack2(xv, xv);
                fma2(acc[i][0], x2, wA);
                fma2(acc[i][1], x2, wB);
            }
        }
        __syncthreads();
    }

    #pragma unroll
    for (int i = 0; i < 4; i++) {
        int node = nb + ty * 4 + i;
        if (node < N_NODES) {
            float2 a = unpack2(acc[i][0]);
            float2 b = unpack2(acc[i][1]);
            float4 v = make_float4(a.x, a.y, b.x, b.y);
            *reinterpret_cast<float4*>(&g_h[(size_t)node * OUT_CH + tx * 4]) = v;
        }
    }
}

// ---------------------------------------------------------------------------
// 6) atomic-free gather (R7-proven shape): one warp per node, lane owns 2
//    channels (float2), whole warp reads one coherent 256B h-row per edge,
//    edge record broadcast. Deepened to 4-wide unroll for MLP.
// ---------------------------------------------------------------------------
__global__ void __launch_bounds__(256) k_gather(const float* __restrict__ b,
                                                float* __restrict__ out) {
    int warp = (blockIdx.x * blockDim.x + threadIdx.x) >> 5;
    int lane = threadIdx.x & 31;
    if (warp >= N_NODES) return;

    int end = g_off[warp];          // post-fill cursor = end
    int deg = g_cnt[warp];
    const int2* ep = g_edge + (end - deg);
    const float2* h2 = reinterpret_cast<const float2*>(g_h);

    float2 acc = make_float2(0.0f, 0.0f);

    int i = 0;
    for (; i + 4 <= deg; i += 4) {
        int2 p0 = ep[i];
        int2 p1 = ep[i + 1];
        int2 p2 = ep[i + 2];
        int2 p3 = ep[i + 3];
        float2 h0 = h2[(size_t)p0.x * (OUT_CH / 2) + lane];
        float2 h1 = h2[(size_t)p1.x * (OUT_CH / 2) + lane];
        float2 h3v = h2[(size_t)p3.x * (OUT_CH / 2) + lane];
        float2 h2v = h2[(size_t)p2.x * (OUT_CH / 2) + lane];
        float s0 = __int_as_float(p0.y);
        float s1 = __int_as_float(p1.y);
        float s2 = __int_as_float(p2.y);
        float s3 = __int_as_float(p3.y);
        acc.x += h0.x * s0 + h1.x * s1 + h2v.x * s2 + h3v.x * s3;
        acc.y += h0.y * s0 + h1.y * s1 + h2v.y * s2 + h3v.y * s3;
    }
    for (; i < deg; i++) {
        int2 p0 = ep[i];
        float s0 = __int_as_float(p0.y);
        float2 h0 = h2[(size_t)p0.x * (OUT_CH / 2) + lane];
        acc.x += h0.x * s0; acc.y += h0.y * s0;
    }

    float dr = g_dis[warp];
    float2 bv = *reinterpret_cast<const float2*>(&b[lane * 2]);
    float2 o = make_float2(acc.x * dr + bv.x, acc.y * dr + bv.y);
    *reinterpret_cast<float2*>(&out[(size_t)warp * OUT_CH + lane * 2]) = o;
}

// ---------------------------------------------------------------------------
// launch
// ---------------------------------------------------------------------------
extern "C" void kernel_launch(void* const* d_in, const int* in_sizes, int n_in,
                              void* d_out, int out_size) {
    const float* x  = (const float*)d_in[0];
    const int*   ei = (const int*)d_in[1];     // int32 view; layout detected on-device
    const float* ew = (const float*)d_in[2];
    const float* W  = (const float*)d_in[3];
    const float* b  = (const float*)d_in[4];
    float* out = (float*)d_out;

    k_zero_detect<<<(N_NODES + 255) / 256, 256>>>(ei);
    k_deg_accum<<<(N_EDGES + 255) / 256, 256>>>(ei, ew);

    // CSR build (scan1 also finalizes deg^-1/2)
    k_scan1<<<N_SCAN_BLK, SCAN_BLK>>>();
    k_scan2<<<1, 128>>>();
    k_scan3<<<N_SCAN_BLK, SCAN_BLK>>>();
    k_fill<<<(N_EDGES + 255) / 256, 256>>>(ei);

    // dense transform
    k_gemm<<<(N_NODES + 63) / 64, 256>>>(x, W);

    // atomic-free aggregate + bias
    int gather_blocks = (N_NODES * 32 + 255) / 256;
    k_gather<<<gather_blocks, 256>>>(b, out);
}

// round 10
// speedup vs baseline: 1.5467x; 1.1345x over previous
#include <cuda_runtime.h>
#include <cuda_bf16.h>
#include <cstdint>

// Problem constants (fixed by the dataset)
#define N_NODES 100000
#define N_EDGES 1250000
#define IN_CH   128
#define OUT_CH  64

// Scratch (no cudaMalloc allowed)
__device__ __align__(16) float g_h[(size_t)N_NODES * OUT_CH];   // 25.6 MB
__device__ float g_dis[N_NODES];            // deg, then deg^-1/2
__device__ int   g_cnt[N_NODES];            // in-degree (edge count)
__device__ int   g_off[N_NODES];            // excl. base -> end cursor after fill
__device__ int   g_total;                   // global segment cursor
__device__ __align__(8) int2 g_edge[N_EDGES]; // CSR payload: {col, bits(dis[col])}
__device__ int   g_is64;                    // 1 if edge_index stored as int64

// ---------------------------------------------------------------------------
// Edge-index access through an int32 view, layout-agnostic.
// ---------------------------------------------------------------------------
__device__ __forceinline__ int edge_row(const int* __restrict__ w, int e, int is64) {
    return is64 ? w[2 * e] : w[e];
}
__device__ __forceinline__ int edge_col(const int* __restrict__ w, int e, int is64) {
    return is64 ? w[2 * (N_EDGES + e)] : w[N_EDGES + e];
}

// ---------------------------------------------------------------------------
// f32x2 packed-FMA helpers (sm_100+; ptxas emits FFMA2). Compute-only asm.
// ---------------------------------------------------------------------------
__device__ __forceinline__ void fma2(unsigned long long& acc,
                                     unsigned long long a,
                                     unsigned long long b) {
    asm("fma.rn.f32x2 %0, %1, %2, %0;" : "+l"(acc) : "l"(a), "l"(b));
}
__device__ __forceinline__ unsigned long long pack2(float lo, float hi) {
    unsigned long long r;
    asm("mov.b64 %0, {%1, %2};" : "=l"(r) : "f"(lo), "f"(hi));
    return r;
}
__device__ __forceinline__ float2 unpack2(unsigned long long v) {
    float2 f;
    asm("mov.b64 {%0, %1}, %2;" : "=f"(f.x), "=f"(f.y) : "l"(v));
    return f;
}

// ---------------------------------------------------------------------------
// 1) zero degree/count buffers + global cursor; block 0 detects dtype
// ---------------------------------------------------------------------------
__global__ void k_zero_detect(const int* __restrict__ w) {
    __shared__ int nz;
    int i = blockIdx.x * blockDim.x + threadIdx.x;
    if (i < N_NODES) { g_dis[i] = 0.0f; g_cnt[i] = 0; }
    if (i == 0) g_total = 0;
    if (blockIdx.x == 0) {
        if (threadIdx.x == 0) nz = 0;
        __syncthreads();
        int bad = 0;
        #pragma unroll
        for (int j = 0; j < 4; j++) {
            int idx = 2 * (threadIdx.x + j * 256) + 1;
            if (w[idx] != 0) bad = 1;
        }
        if (bad) atomicOr(&nz, 1);
        __syncthreads();
        if (threadIdx.x == 0) g_is64 = (nz == 0) ? 1 : 0;
    }
}

// ---------------------------------------------------------------------------
// 2) fused weighted in-degree + edge histogram
// ---------------------------------------------------------------------------
__global__ void k_deg_accum(const int* __restrict__ ei,
                            const float* __restrict__ ew) {
    int e = blockIdx.x * blockDim.x + threadIdx.x;
    if (e < N_EDGES) {
        int is64 = g_is64;
        int r = edge_row(ei, e, is64);
        if ((unsigned)r < N_NODES) {
            atomicAdd(&g_dis[r], ew[e]);
            atomicAdd(&g_cnt[r], 1);
        }
    }
}

// ---------------------------------------------------------------------------
// 3) segment allocation (replaces 3-kernel scan): warp-inclusive scan of
//    counts, one global atomicAdd per warp for the base, exclusive offsets
//    out. CSR segments land in allocation order (gather only needs
//    per-node contiguity, not node order). Fuses deg -> deg^-1/2.
// ---------------------------------------------------------------------------
__global__ void __launch_bounds__(256) k_alloc() {
    int i = blockIdx.x * blockDim.x + threadIdx.x;
    int lane = threadIdx.x & 31;
    int c = (i < N_NODES) ? g_cnt[i] : 0;

    // warp inclusive scan
    int pre = c;
    #pragma unroll
    for (int off = 1; off < 32; off <<= 1) {
        int y = __shfl_up_sync(0xffffffffu, pre, off);
        if (lane >= off) pre += y;
    }
    int wsum = __shfl_sync(0xffffffffu, pre, 31);
    int base = 0;
    if (lane == 31) base = atomicAdd(&g_total, wsum);
    base = __shfl_sync(0xffffffffu, base, 31);

    if (i < N_NODES) {
        g_off[i] = base + pre - c;     // exclusive within warp
        float d = g_dis[i];
        g_dis[i] = (d > 0.0f) ? rsqrtf(d) : 0.0f;
    }
}

// ---------------------------------------------------------------------------
// 4) CSR fill: g_off used as cursor; after this, g_off[r] = end of node r.
// ---------------------------------------------------------------------------
__global__ void k_fill(const int* __restrict__ ei) {
    int e = blockIdx.x * blockDim.x + threadIdx.x;
    if (e < N_EDGES) {
        int is64 = g_is64;
        int r   = edge_row(ei, e, is64);
        int col = edge_col(ei, e, is64);
        if ((unsigned)r >= N_NODES || (unsigned)col >= N_NODES) return;
        int pos = atomicAdd(&g_off[r], 1);
        g_edge[pos] = make_int2(col, __float_as_int(g_dis[col]));
    }
}

// ---------------------------------------------------------------------------
// 5) GEMM: g_h[100000,64] = x[100000,128] @ W[128,64]  (FFMA2, tiled)
//    Independent of the CSR chain -> runs on a side stream.
// ---------------------------------------------------------------------------
#define XS_STRIDE 68

__global__ void __launch_bounds__(256) k_gemm(const float* __restrict__ x,
                                              const float* __restrict__ W) {
    __shared__ __align__(16) float Ws[IN_CH * OUT_CH];   // 32 KB
    __shared__ __align__(16) float Xs[64 * XS_STRIDE];   // 17 KB

    const int t  = threadIdx.x;
    const int tx = t & 15;
    const int ty = t >> 4;
    const int nb = blockIdx.x * 64;

    {
        const float4* W4 = reinterpret_cast<const float4*>(W);
        float4* Ws4 = reinterpret_cast<float4*>(Ws);
        #pragma unroll
        for (int i = 0; i < (IN_CH * OUT_CH / 4) / 256; i++)
            Ws4[t + i * 256] = W4[t + i * 256];
    }

    unsigned long long acc[4][2];
    #pragma unroll
    for (int i = 0; i < 4; i++) { acc[i][0] = 0ull; acc[i][1] = 0ull; }

    #pragma unroll
    for (int kc = 0; kc < 2; kc++) {
        {
            const float4* x4 = reinterpret_cast<const float4*>(x);
            #pragma unroll
            for (int i = 0; i < 4; i++) {
                int f = t + i * 256;
                int node = f >> 4;
                int kk4  = f & 15;
                int gn = nb + node;
                float4 v = make_float4(0.f, 0.f, 0.f, 0.f);
                if (gn < N_NODES)
                    v = x4[(size_t)gn * (IN_CH / 4) + kc * 16 + kk4];
                *reinterpret_cast<float4*>(&Xs[node * XS_STRIDE + kk4 * 4]) = v;
            }
        }
        __syncthreads();

        #pragma unroll 8
        for (int kk = 0; kk < 64; kk++) {
            float4 w = *reinterpret_cast<const float4*>(
                &Ws[(kc * 64 + kk) * OUT_CH + tx * 4]);
            unsigned long long wA = pack2(w.x, w.y);
            unsigned long long wB = pack2(w.z, w.w);
            #pragma unroll
            for (int i = 0; i < 4; i++) {
                float xv = Xs[(ty * 4 + i) * XS_STRIDE + kk];
                unsigned long long x2 = pack2(xv, xv);
                fma2(acc[i][0], x2, wA);
                fma2(acc[i][1], x2, wB);
            }
        }
        __syncthreads();
    }

    #pragma unroll
    for (int i = 0; i < 4; i++) {
        int node = nb + ty * 4 + i;
        if (node < N_NODES) {
            float2 a = unpack2(acc[i][0]);
            float2 b = unpack2(acc[i][1]);
            float4 v = make_float4(a.x, a.y, b.x, b.y);
            *reinterpret_cast<float4*>(&g_h[(size_t)node * OUT_CH + tx * 4]) = v;
        }
    }
}

// ---------------------------------------------------------------------------
// 6) atomic-free gather (R7/R9-proven shape): one warp per node, lane owns
//    2 channels, coherent 256B h-row per edge, 4-wide unroll for MLP.
// ---------------------------------------------------------------------------
__global__ void __launch_bounds__(256) k_gather(const float* __restrict__ b,
                                                float* __restrict__ out) {
    int warp = (blockIdx.x * blockDim.x + threadIdx.x) >> 5;
    int lane = threadIdx.x & 31;
    if (warp >= N_NODES) return;

    int end = g_off[warp];          // post-fill cursor = end
    int deg = g_cnt[warp];
    const int2* ep = g_edge + (end - deg);
    const float2* h2 = reinterpret_cast<const float2*>(g_h);

    float2 acc = make_float2(0.0f, 0.0f);

    int i = 0;
    for (; i + 4 <= deg; i += 4) {
        int2 p0 = ep[i];
        int2 p1 = ep[i + 1];
        int2 p2 = ep[i + 2];
        int2 p3 = ep[i + 3];
        float2 h0 = h2[(size_t)p0.x * (OUT_CH / 2) + lane];
        float2 h1 = h2[(size_t)p1.x * (OUT_CH / 2) + lane];
        float2 h3v = h2[(size_t)p3.x * (OUT_CH / 2) + lane];
        float2 h2v = h2[(size_t)p2.x * (OUT_CH / 2) + lane];
        float s0 = __int_as_float(p0.y);
        float s1 = __int_as_float(p1.y);
        float s2 = __int_as_float(p2.y);
        float s3 = __int_as_float(p3.y);
        acc.x += h0.x * s0 + h1.x * s1 + h2v.x * s2 + h3v.x * s3;
        acc.y += h0.y * s0 + h1.y * s1 + h2v.y * s2 + h3v.y * s3;
    }
    for (; i < deg; i++) {
        int2 p0 = ep[i];
        float s0 = __int_as_float(p0.y);
        float2 h0 = h2[(size_t)p0.x * (OUT_CH / 2) + lane];
        acc.x += h0.x * s0; acc.y += h0.y * s0;
    }

    float dr = g_dis[warp];
    float2 bv = *reinterpret_cast<const float2*>(&b[lane * 2]);
    float2 o = make_float2(acc.x * dr + bv.x, acc.y * dr + bv.y);
    *reinterpret_cast<float2*>(&out[(size_t)warp * OUT_CH + lane * 2]) = o;
}

// ---------------------------------------------------------------------------
// launch: CSR chain on the launch stream, GEMM forked onto a side stream
// (capture-legal event fork/join). Handles created once; no device memory.
// ---------------------------------------------------------------------------
extern "C" void kernel_launch(void* const* d_in, const int* in_sizes, int n_in,
                              void* d_out, int out_size) {
    const float* x  = (const float*)d_in[0];
    const int*   ei = (const int*)d_in[1];     // int32 view; layout detected on-device
    const float* ew = (const float*)d_in[2];
    const float* W  = (const float*)d_in[3];
    const float* b  = (const float*)d_in[4];
    float* out = (float*)d_out;

    static cudaStream_t s_side = nullptr;
    static cudaEvent_t  s_fork = nullptr, s_join = nullptr;
    if (s_side == nullptr) {
        cudaStreamCreateWithFlags(&s_side, cudaStreamNonBlocking);
        cudaEventCreateWithFlags(&s_fork, cudaEventDisableTiming);
        cudaEventCreateWithFlags(&s_join, cudaEventDisableTiming);
    }

    // Fork: GEMM depends on nothing in the CSR chain.
    cudaEventRecord(s_fork, 0);
    cudaStreamWaitEvent(s_side, s_fork, 0);
    k_gemm<<<(N_NODES + 63) / 64, 256, 0, s_side>>>(x, W);
    cudaEventRecord(s_join, s_side);

    // CSR chain on the launch stream.
    k_zero_detect<<<(N_NODES + 255) / 256, 256>>>(ei);
    k_deg_accum<<<(N_EDGES + 255) / 256, 256>>>(ei, ew);
    k_alloc<<<(N_NODES + 255) / 256, 256>>>();
    k_fill<<<(N_EDGES + 255) / 256, 256>>>(ei);

    // Join: gather needs both g_h (GEMM) and the CSR.
    cudaStreamWaitEvent(0, s_join, 0);
    int gather_blocks = (N_NODES * 32 + 255) / 256;
    k_gather<<<gather_blocks, 256>>>(b, out);
}